// round 7
// baseline (speedup 1.0000x reference)
#include <cuda_runtime.h>
#include <cuda_bf16.h>
#include <cstdint>

#define N_NODES 100000
#define N_EDGES 3200000
#define IN_F    256
#define OUT_F   64
#define ALPHA   0.2f

// ---------------- device scratch (no allocs allowed) ----------------
__device__ float g_h[(size_t)N_NODES * OUT_F];    // h = input @ W
__device__ float g_acc[(size_t)N_NODES * OUT_F];  // accumulator (GPU-local)
__device__ float g_ss[N_NODES];                   // s_src per node
__device__ float g_sd[N_NODES];                   // s_dst per node
__device__ float g_rowsum[N_NODES];               // segment sum of edge_e by src
__device__ int   g_is64;                          // edge dtype flag

// ---------------- K-1: detect edge dtype (int32 vs int64) ----------------
// int64 little-endian with ids < 2^31 => every odd int32 word is 0.
__global__ void k_detect(const int* __restrict__ ev) {
    __shared__ unsigned s[2];
    int k = threadIdx.x * 9973;                  // sample spread over first edges
    int val = ev[2 * k + 1];
    unsigned nz = __ballot_sync(0xffffffffu, val != 0);
    if ((threadIdx.x & 31) == 0) s[threadIdx.x >> 5] = nz;
    __syncthreads();
    if (threadIdx.x == 0) g_is64 = ((s[0] | s[1]) == 0u) ? 1 : 0;
}

// ---------------- K0: zero accumulators ----------------
__global__ void k_zero() {
    int i = blockIdx.x * blockDim.x + threadIdx.x;
    const int total = N_NODES * OUT_F;
    if (i < total) g_acc[i] = 0.0f;
    else if (i < total + N_NODES) g_rowsum[i - total] = 0.0f;
}

// ---------------- K1: tiled fp32 GEMM  h = input @ W ----------------
__global__ __launch_bounds__(256) void k_gemm(const float* __restrict__ A,
                                              const float* __restrict__ W) {
    __shared__ float As[64][33];
    __shared__ float Bs[32][64];

    const int bm  = blockIdx.x * 64;
    const int tid = threadIdx.x;
    const int tx  = tid & 15;
    const int ty  = tid >> 4;

    float acc[4][4];
#pragma unroll
    for (int i = 0; i < 4; i++)
#pragma unroll
        for (int j = 0; j < 4; j++) acc[i][j] = 0.0f;

    for (int k0 = 0; k0 < IN_F; k0 += 32) {
#pragma unroll
        for (int it = 0; it < 2; it++) {
            int idx = tid + it * 256;
            int m   = idx >> 3;
            int kq  = (idx & 7) << 2;
            int node = bm + m;
            float4 v = make_float4(0.f, 0.f, 0.f, 0.f);
            if (node < N_NODES)
                v = *(const float4*)&A[(size_t)node * IN_F + k0 + kq];
            As[m][kq + 0] = v.x; As[m][kq + 1] = v.y;
            As[m][kq + 2] = v.z; As[m][kq + 3] = v.w;
        }
#pragma unroll
        for (int it = 0; it < 2; it++) {
            int idx = tid + it * 256;
            int kk  = idx >> 4;
            int nn  = (idx & 15) << 2;
            *(float4*)&Bs[kk][nn] = *(const float4*)&W[(size_t)(k0 + kk) * OUT_F + nn];
        }
        __syncthreads();

#pragma unroll
        for (int k = 0; k < 32; k++) {
            float a0 = As[ty * 4 + 0][k];
            float a1 = As[ty * 4 + 1][k];
            float a2 = As[ty * 4 + 2][k];
            float a3 = As[ty * 4 + 3][k];
            float4 b = *(const float4*)&Bs[k][tx * 4];
            acc[0][0] += a0 * b.x; acc[0][1] += a0 * b.y; acc[0][2] += a0 * b.z; acc[0][3] += a0 * b.w;
            acc[1][0] += a1 * b.x; acc[1][1] += a1 * b.y; acc[1][2] += a1 * b.z; acc[1][3] += a1 * b.w;
            acc[2][0] += a2 * b.x; acc[2][1] += a2 * b.y; acc[2][2] += a2 * b.z; acc[2][3] += a2 * b.w;
            acc[3][0] += a3 * b.x; acc[3][1] += a3 * b.y; acc[3][2] += a3 * b.z; acc[3][3] += a3 * b.w;
        }
        __syncthreads();
    }

#pragma unroll
    for (int i = 0; i < 4; i++) {
        int node = bm + ty * 4 + i;
        if (node < N_NODES) {
            float4 v = make_float4(acc[i][0], acc[i][1], acc[i][2], acc[i][3]);
            *(float4*)&g_h[(size_t)node * OUT_F + tx * 4] = v;
        }
    }
}

// ---------------- K2: per-node attention scores ----------------
__global__ __launch_bounds__(256) void k_scores(const float* __restrict__ a) {
    int node = blockIdx.x * 8 + (threadIdx.x >> 5);
    int lane = threadIdx.x & 31;
    if (node >= N_NODES) return;
    float2 h2  = *(const float2*)&g_h[(size_t)node * OUT_F + lane * 2];
    float2 as2 = *(const float2*)&a[lane * 2];
    float2 ad2 = *(const float2*)&a[OUT_F + lane * 2];
    float vs = h2.x * as2.x + h2.y * as2.y;
    float vd = h2.x * ad2.x + h2.y * ad2.y;
#pragma unroll
    for (int o = 16; o > 0; o >>= 1) {
        vs += __shfl_xor_sync(0xffffffffu, vs, o);
        vd += __shfl_xor_sync(0xffffffffu, vd, o);
    }
    if (lane == 0) { g_ss[node] = vs; g_sd[node] = vd; }
}

// ---------------- K3: edge gather + atomic scatter ----------------
// Half-warp (16 lanes) per edge; one float4 of the 64 feats per lane.
__global__ __launch_bounds__(256) void k_edge(const int* __restrict__ ev) {
    const int is64 = g_is64;
    const int lane = threadIdx.x & 31;
    const int half = lane >> 4;
    const int hl   = lane & 15;
    int hw_id   = (blockIdx.x * (blockDim.x >> 5) + (threadIdx.x >> 5)) * 2 + half;
    int n_hw    = gridDim.x * (blockDim.x >> 5) * 2;

    for (int e = hw_id; e < N_EDGES; e += n_hw) {
        int src, dst;
        if (is64) {                       // int64 array viewed as int32 pairs
            src = ev[2 * (size_t)e];
            dst = ev[2 * ((size_t)N_EDGES + e)];
        } else {                          // native int32
            src = ev[e];
            dst = ev[N_EDGES + e];
        }
        src = min(max(src, 0), N_NODES - 1);
        dst = min(max(dst, 0), N_NODES - 1);

        float score = g_ss[src] + g_sd[dst];
        float lrelu = score >= 0.f ? score : ALPHA * score;
        float ev_w  = __expf(-lrelu);

        float4 hv = *(const float4*)&g_h[(size_t)dst * OUT_F + hl * 4];
        float* p  = &g_acc[(size_t)src * OUT_F + hl * 4];
        atomicAdd(p + 0, hv.x * ev_w);
        atomicAdd(p + 1, hv.y * ev_w);
        atomicAdd(p + 2, hv.z * ev_w);
        atomicAdd(p + 3, hv.w * ev_w);
        if (hl == 0) atomicAdd(&g_rowsum[src], ev_w);
    }
}

// ---------------- K4: finalize out = elu(acc / rowsum) ----------------
__global__ __launch_bounds__(256) void k_final(float* __restrict__ out) {
    int i = blockIdx.x * blockDim.x + threadIdx.x;
    if (i >= N_NODES * OUT_F) return;
    int node = i >> 6;
    float v = g_acc[i] / g_rowsum[node];
    out[i] = v > 0.f ? v : (__expf(v) - 1.0f);
}

// ---------------- launch ----------------
extern "C" void kernel_launch(void* const* d_in, const int* in_sizes, int n_in,
                              void* d_out, int out_size) {
    const float* input = (const float*)d_in[0];
    const int*   edge  = (const int*)d_in[1];   // int32 view (works for int64 too)
    const float* W     = (const float*)d_in[2];
    const float* a     = (const float*)d_in[3];
    float*       out   = (float*)d_out;

    k_detect<<<1, 64>>>(edge);
    const int total_zero = N_NODES * OUT_F + N_NODES;
    k_zero<<<(total_zero + 255) / 256, 256>>>();
    k_gemm<<<(N_NODES + 63) / 64, 256>>>(input, W);
    k_scores<<<(N_NODES + 7) / 8, 256>>>(a);
    k_edge<<<2048, 256>>>(edge);
    k_final<<<(N_NODES * OUT_F + 255) / 256, 256>>>(out);
}

// round 8
// speedup vs baseline: 1.7102x; 1.7102x over previous
#include <cuda_runtime.h>
#include <cuda_bf16.h>
#include <cstdint>

#define N_NODES 100000
#define N_EDGES 3200000
#define IN_F    256
#define OUT_F   64
#define ALPHA   0.2f

// ---------------- device scratch (no allocs allowed) ----------------
__device__ float g_h[(size_t)N_NODES * OUT_F];    // h = input @ W
__device__ float g_acc[(size_t)N_NODES * OUT_F];  // accumulator (GPU-local)
__device__ float g_ss[N_NODES];                   // s_src per node
__device__ float g_sd[N_NODES];                   // s_dst per node
__device__ float g_rowsum[N_NODES];               // segment sum of edge_e by src
__device__ int   g_is64;                          // edge dtype flag

// ---------------- K-1: detect edge dtype (int32 vs int64) ----------------
// int64 little-endian with ids < 2^31 => every odd int32 word is 0.
__global__ void k_detect(const int* __restrict__ ev) {
    __shared__ unsigned s[2];
    int k = threadIdx.x * 9973;                  // sample spread over first edges
    int val = ev[2 * k + 1];
    unsigned nz = __ballot_sync(0xffffffffu, val != 0);
    if ((threadIdx.x & 31) == 0) s[threadIdx.x >> 5] = nz;
    __syncthreads();
    if (threadIdx.x == 0) g_is64 = ((s[0] | s[1]) == 0u) ? 1 : 0;
}

// ---------------- K0: zero accumulators ----------------
__global__ void k_zero() {
    int i = blockIdx.x * blockDim.x + threadIdx.x;
    const int total = N_NODES * OUT_F;
    if (i < total) g_acc[i] = 0.0f;
    else if (i < total + N_NODES) g_rowsum[i - total] = 0.0f;
}

// ---------------- K1: tiled fp32 GEMM  h = input @ W ----------------
__global__ __launch_bounds__(256) void k_gemm(const float* __restrict__ A,
                                              const float* __restrict__ W) {
    __shared__ float As[64][33];
    __shared__ float Bs[32][64];

    const int bm  = blockIdx.x * 64;
    const int tid = threadIdx.x;
    const int tx  = tid & 15;
    const int ty  = tid >> 4;

    float acc[4][4];
#pragma unroll
    for (int i = 0; i < 4; i++)
#pragma unroll
        for (int j = 0; j < 4; j++) acc[i][j] = 0.0f;

    for (int k0 = 0; k0 < IN_F; k0 += 32) {
#pragma unroll
        for (int it = 0; it < 2; it++) {
            int idx = tid + it * 256;
            int m   = idx >> 3;
            int kq  = (idx & 7) << 2;
            int node = bm + m;
            float4 v = make_float4(0.f, 0.f, 0.f, 0.f);
            if (node < N_NODES)
                v = *(const float4*)&A[(size_t)node * IN_F + k0 + kq];
            As[m][kq + 0] = v.x; As[m][kq + 1] = v.y;
            As[m][kq + 2] = v.z; As[m][kq + 3] = v.w;
        }
#pragma unroll
        for (int it = 0; it < 2; it++) {
            int idx = tid + it * 256;
            int kk  = idx >> 4;
            int nn  = (idx & 15) << 2;
            *(float4*)&Bs[kk][nn] = *(const float4*)&W[(size_t)(k0 + kk) * OUT_F + nn];
        }
        __syncthreads();

#pragma unroll
        for (int k = 0; k < 32; k++) {
            float a0 = As[ty * 4 + 0][k];
            float a1 = As[ty * 4 + 1][k];
            float a2 = As[ty * 4 + 2][k];
            float a3 = As[ty * 4 + 3][k];
            float4 b = *(const float4*)&Bs[k][tx * 4];
            acc[0][0] += a0 * b.x; acc[0][1] += a0 * b.y; acc[0][2] += a0 * b.z; acc[0][3] += a0 * b.w;
            acc[1][0] += a1 * b.x; acc[1][1] += a1 * b.y; acc[1][2] += a1 * b.z; acc[1][3] += a1 * b.w;
            acc[2][0] += a2 * b.x; acc[2][1] += a2 * b.y; acc[2][2] += a2 * b.z; acc[2][3] += a2 * b.w;
            acc[3][0] += a3 * b.x; acc[3][1] += a3 * b.y; acc[3][2] += a3 * b.z; acc[3][3] += a3 * b.w;
        }
        __syncthreads();
    }

#pragma unroll
    for (int i = 0; i < 4; i++) {
        int node = bm + ty * 4 + i;
        if (node < N_NODES) {
            float4 v = make_float4(acc[i][0], acc[i][1], acc[i][2], acc[i][3]);
            *(float4*)&g_h[(size_t)node * OUT_F + tx * 4] = v;
        }
    }
}

// ---------------- K2: per-node attention scores ----------------
__global__ __launch_bounds__(256) void k_scores(const float* __restrict__ a) {
    int node = blockIdx.x * 8 + (threadIdx.x >> 5);
    int lane = threadIdx.x & 31;
    if (node >= N_NODES) return;
    float2 h2  = *(const float2*)&g_h[(size_t)node * OUT_F + lane * 2];
    float2 as2 = *(const float2*)&a[lane * 2];
    float2 ad2 = *(const float2*)&a[OUT_F + lane * 2];
    float vs = h2.x * as2.x + h2.y * as2.y;
    float vd = h2.x * ad2.x + h2.y * ad2.y;
#pragma unroll
    for (int o = 16; o > 0; o >>= 1) {
        vs += __shfl_xor_sync(0xffffffffu, vs, o);
        vd += __shfl_xor_sync(0xffffffffu, vd, o);
    }
    if (lane == 0) { g_ss[node] = vs; g_sd[node] = vd; }
}

// ---------------- K3: edge gather + vectorized atomic scatter ----------------
// Half-warp (16 lanes) per edge; one float4 of the 64 feats per lane.
// red.global.add.v4.f32 issues ONE instruction per 16 bytes (4x fewer REDG lanes).
__global__ __launch_bounds__(256) void k_edge(const int* __restrict__ ev) {
    const int is64 = g_is64;
    const int lane = threadIdx.x & 31;
    const int half = lane >> 4;
    const int hl   = lane & 15;
    int hw_id   = (blockIdx.x * (blockDim.x >> 5) + (threadIdx.x >> 5)) * 2 + half;
    int n_hw    = gridDim.x * (blockDim.x >> 5) * 2;

    for (int e = hw_id; e < N_EDGES; e += n_hw) {
        int src, dst;
        if (is64) {                       // int64 array viewed as int32 pairs
            src = ev[2 * (size_t)e];
            dst = ev[2 * ((size_t)N_EDGES + e)];
        } else {                          // native int32
            src = ev[e];
            dst = ev[N_EDGES + e];
        }
        src = min(max(src, 0), N_NODES - 1);
        dst = min(max(dst, 0), N_NODES - 1);

        float score = g_ss[src] + g_sd[dst];
        float lrelu = score >= 0.f ? score : ALPHA * score;
        float ev_w  = __expf(-lrelu);

        float4 hv = *(const float4*)&g_h[(size_t)dst * OUT_F + hl * 4];
        float* p  = &g_acc[(size_t)src * OUT_F + hl * 4];
        asm volatile("red.global.add.v4.f32 [%0], {%1, %2, %3, %4};"
                     :: "l"(p), "f"(hv.x * ev_w), "f"(hv.y * ev_w),
                        "f"(hv.z * ev_w), "f"(hv.w * ev_w)
                     : "memory");
        if (hl == 0) atomicAdd(&g_rowsum[src], ev_w);
    }
}

// ---------------- K4: finalize out = elu(acc / rowsum) ----------------
__global__ __launch_bounds__(256) void k_final(float* __restrict__ out) {
    int i = blockIdx.x * blockDim.x + threadIdx.x;
    if (i >= N_NODES * OUT_F) return;
    int node = i >> 6;
    float v = g_acc[i] / g_rowsum[node];
    out[i] = v > 0.f ? v : (__expf(v) - 1.0f);
}

// ---------------- launch ----------------
extern "C" void kernel_launch(void* const* d_in, const int* in_sizes, int n_in,
                              void* d_out, int out_size) {
    const float* input = (const float*)d_in[0];
    const int*   edge  = (const int*)d_in[1];   // int32 view (works for int64 too)
    const float* W     = (const float*)d_in[2];
    const float* a     = (const float*)d_in[3];
    float*       out   = (float*)d_out;

    k_detect<<<1, 64>>>(edge);
    const int total_zero = N_NODES * OUT_F + N_NODES;
    k_zero<<<(total_zero + 255) / 256, 256>>>();
    k_gemm<<<(N_NODES + 63) / 64, 256>>>(input, W);
    k_scores<<<(N_NODES + 7) / 8, 256>>>(a);
    k_edge<<<2048, 256>>>(edge);
    k_final<<<(N_NODES * OUT_F + 255) / 256, 256>>>(out);
}